// round 13
// baseline (speedup 1.0000x reference)
#include <cuda_runtime.h>
#include <math_constants.h>

#define HH 224
#define WW 224
#define HWP (HH * WW)      // 50176
#define BB 64
#define RBLK 16            // reduce-role blocks per batch
#define NRED (BB * RBLK)   // 1024
#define FBLK 49            // fill-role blocks per batch
#define NFILL (BB * FBLK)  // 3136
#define NQ (HWP / 4)       // 12544 float4 tiles per image
#define CGRID 1184         // cone kernel: 148 SMs * 8 blocks, one full wave

// Per-(batch, block) partial min/max. Plain stores (no init needed).
__device__ float g_pmax[BB][RBLK];
__device__ float g_pmin[BB][RBLK];
// Tickets. Zero at module load; winners reset -> replay-safe.
__device__ int g_cnt[BB];
__device__ int g_done2;
// Per-batch scalars: [pd, fr, hp0f, hp1f] [gx, gy, rn2, pad]
__device__ float4 g_scal[BB][2];
// Worklist of in-cone float4 tiles: entry = (b << 14) | tile_idx.
__device__ int g_wl_cnt;
__device__ int g_wl[BB * NQ];

// ---------------------------------------------------------------------------
// Kernel 1: reduce role + fill role, zero coupling (no flags, no spinning).
// Fill writes zeros everywhere (valid for the ~92% out-of-cone pixels,
// overwritten for the rest by kernel 2) and pushes in-cone tiles to a
// compacted worklist so kernel 2's threads are ALL heavy-path (no
// divergence blowup from the wedge crossing warp-wide row segments).
// ---------------------------------------------------------------------------
__global__ void __launch_bounds__(256)
fused_kernel(const float* __restrict__ depth, const float* __restrict__ obj,
             const float* __restrict__ gaze, const long long* __restrict__ hp,
             float* __restrict__ out) {
    const int bid = blockIdx.x;

    if (bid < NRED) {
        // ------------- reduce role -------------
        const int b    = bid / RBLK;
        const int rblk = bid % RBLK;

        // Thread 0 prefetches scalar inputs at entry; the dependent chain
        // (hp -> head pixel -> product) overlaps the reduction loop.
        int hp0 = 0, hp1 = 0;
        float gx = 0.f, gy = 0.f, gz = 0.f, hd = 0.f;
        if (threadIdx.x == 0) {
            hp0 = (int)hp[2 * b];
            hp1 = (int)hp[2 * b + 1];
            gx = gaze[3 * b]; gy = gaze[3 * b + 1]; gz = gaze[3 * b + 2];
            size_t hidx = (size_t)b * HWP + (size_t)hp0 * WW + hp1;
            hd = depth[hidx] * obj[hidx];
        }

        const float4* dp = reinterpret_cast<const float4*>(depth + (size_t)b * HWP);
        const float4* op = reinterpret_cast<const float4*>(obj + (size_t)b * HWP);
        float mx = -CUDART_INF_F, mn = CUDART_INF_F;
        for (int i = rblk * 256 + threadIdx.x; i < NQ; i += RBLK * 256) {
            float4 d = dp[i];
            float4 o = op[i];
            float p0 = d.x * o.x, p1 = d.y * o.y, p2 = d.z * o.z, p3 = d.w * o.w;
            mx = fmaxf(mx, fmaxf(fmaxf(p0, p1), fmaxf(p2, p3)));
            mn = fminf(mn, fminf(fminf(p0, p1), fminf(p2, p3)));
        }
#pragma unroll
        for (int off = 16; off; off >>= 1) {
            mx = fmaxf(mx, __shfl_xor_sync(0xffffffffu, mx, off));
            mn = fminf(mn, __shfl_xor_sync(0xffffffffu, mn, off));
        }
        __shared__ float smx[8], smn[8];
        int w = threadIdx.x >> 5, l = threadIdx.x & 31;
        if (l == 0) { smx[w] = mx; smn[w] = mn; }
        __syncthreads();
        if (threadIdx.x == 0) {
#pragma unroll
            for (int i = 1; i < 8; i++) {
                mx = fmaxf(mx, smx[i]);
                mn = fminf(mn, smn[i]);
            }
            g_pmax[b][rblk] = mx;
            g_pmin[b][rblk] = mn;
            __threadfence();
            int ticket = atomicAdd(&g_cnt[b], 1);
            if (ticket == RBLK - 1) {
                g_cnt[b] = 0;        // reset for next graph replay
                float fmx = -CUDART_INF_F, fmn = CUDART_INF_F;
#pragma unroll
                for (int i = 0; i < RBLK; i++) {
                    fmx = fmaxf(fmx, g_pmax[b][i]);
                    fmn = fminf(fmn, g_pmin[b][i]);
                }
                g_scal[b][0] = make_float4(hd + gz * 224.0f,      // pd
                                           (fmx - fmn) / 24.0f,   // fr
                                           (float)hp0, (float)hp1);
                g_scal[b][1] = make_float4(gx, gy, gx * gx + gy * gy, 0.f);
            }
        }
        return;
    }

    // ------------- fill role -------------
    const int mb = bid - NRED;
    const int b  = mb / FBLK;
    const int lb = mb % FBLK;

    const int idx = lb * 256 + threadIdx.x;  // float4 tile in image
    const int pix = idx * 4;
    const int h   = pix / WW;
    const int w0  = pix % WW;

    // Warp-uniform raw scalar loads (broadcast sectors, L2-hot); these do
    // NOT depend on the reduction.
    const float gx = gaze[3 * b];
    const float gy = gaze[3 * b + 1];
    const float hp0f = (float)(int)hp[2 * b];
    const float hp1f = (float)(int)hp[2 * b + 1];
    const float rn2 = gx * gx + gy * gy;

    const float a1   = (float)h - hp1f;
    const float a1gy = a1 * gy;
    const float a1sq = a1 * a1;
    const float a0b  = (float)w0 - hp0f;

    // Conservative FMA-only cone gate (dot>0 && dot^2>c*tt <=> dot*|dot|>c*tt).
    // 0.93 < cos^2(pi/12)=0.93301: strictly looser than the exact test, so fp
    // noise only sends extra tiles to the exact path, never skips a hit.
    bool any = false;
#pragma unroll
    for (int j = 0; j < 4; j++) {
        float a0  = a0b + (float)j;          // exact (small ints in fp32)
        float dot = fmaf(a0, gx, a1gy);
        float tt  = fmaf(a0, a0, a1sq) * rn2;
        any = any || (dot * fabsf(dot) > 0.93f * tt);
    }

    float* op0 = out + (size_t)b * 3 * HWP + pix;
    const float4 z = make_float4(0.f, 0.f, 0.f, 0.f);
    *reinterpret_cast<float4*>(op0)           = z;
    *reinterpret_cast<float4*>(op0 + HWP)     = z;
    *reinterpret_cast<float4*>(op0 + 2 * HWP) = z;

    // Warp-aggregated worklist push.
    unsigned ball = __ballot_sync(0xffffffffu, any);
    if (any) {
        int lane   = threadIdx.x & 31;
        int leader = __ffs(ball) - 1;
        int rank   = __popc(ball & ((1u << lane) - 1));
        int base = 0;
        if (lane == leader) base = atomicAdd(&g_wl_cnt, __popc(ball));
        base = __shfl_sync(ball, base, leader);
        g_wl[base + rank] = (b << 14) | idx;
    }
}

// ---------------------------------------------------------------------------
// Kernel 2: compacted in-cone tiles only, full-occupancy single wave
// (CGRID=1184 blocks >> worklist/256 entries -> <=1 entry per thread).
// acos via 3-term series on its narrow domain r in (0.966, 1]:
//   acos(1-e) = sqrt(2e) * (1 + e/12 + 3e^2/160 + 5e^3/896),  rel err ~2e-7.
// sqrt(e<0 or NaN) -> NaN -> fmaxf scrubs to 0, reproducing the reference's
// arccos(r>1)=NaN -> nan_to_num -> 0 semantics exactly.
// ---------------------------------------------------------------------------
__global__ void __launch_bounds__(256)
cone_kernel(const float* __restrict__ depth, const float* __restrict__ obj,
            float* __restrict__ out) {
    const int cnt = g_wl_cnt;
    const float angscale = 12.0f / CUDART_PI_F;

    for (int i = blockIdx.x * 256 + threadIdx.x; i < cnt; i += CGRID * 256) {
        const int e0  = g_wl[i];
        const int b   = e0 >> 14;
        const int idx = e0 & 16383;
        const int pix = idx * 4;
        const int h   = pix / WW;
        const int w0  = pix % WW;

        const float4 s0 = g_scal[b][0];
        const float4 s1 = g_scal[b][1];
        const float4 d4 = *reinterpret_cast<const float4*>(depth + (size_t)b * HWP + pix);
        const float4 o4 = *reinterpret_cast<const float4*>(obj   + (size_t)b * HWP + pix);

        const float pd = s0.x, fr = s0.y;
        const float cf1 = fr, cf2 = 2.f * fr, cf3 = 3.f * fr;
        const float gx = s1.x, gy = s1.y, rn2 = s1.z;
        const float a1   = (float)h - s0.w;
        const float a1gy = a1 * gy;
        const float a1sq = a1 * a1;
        const float a0b  = (float)w0 - s0.z;

        float dv[4] = {d4.x * o4.x, d4.y * o4.y, d4.z * o4.z, d4.w * o4.w};

        float o0[4], o1[4], o2[4];
#pragma unroll
        for (int j = 0; j < 4; j++) {
            float a0  = a0b + (float)j;
            float dot = fmaf(a0, gx, a1gy);
            float tt  = fmaf(a0, a0, a1sq) * rn2;
            float r   = dot * rsqrtf(tt);
            float e   = 1.0f - r;            // <0 if r>1; NaN if tt==0
            float se  = sqrtf(e + e);        // NaN for e<0 / NaN
            float poly = fmaf(e, fmaf(e, fmaf(e, 0.0055803571f, 0.01875f),
                                      0.0833333333f), 1.0f);
            float ang = se * poly;           // ~acos(r) on (0.966, 1]
            // mask: out-of-cone -> negative -> 0; NaN -> fmaxf -> 0.
            float m = fmaxf(fmaf(-angscale, ang, 1.0f), 0.0f);
            float d = dv[j];
            float ed = fabsf(d - pd);
            float v = d * m;
            o0[j] = (ed <= cf1) ? v : 0.f;
            o1[j] = (ed <= cf2) ? v : 0.f;
            o2[j] = (ed <= cf3) ? v : 0.f;
        }

        float* op0 = out + (size_t)b * 3 * HWP + pix;
        *reinterpret_cast<float4*>(op0)           = make_float4(o0[0], o0[1], o0[2], o0[3]);
        *reinterpret_cast<float4*>(op0 + HWP)     = make_float4(o1[0], o1[1], o1[2], o1[3]);
        *reinterpret_cast<float4*>(op0 + 2 * HWP) = make_float4(o2[0], o2[1], o2[2], o2[3]);
    }

    // Replay reset: every block tickets in (after its loop); the last one
    // clears the worklist counter. All count reads precede the reset.
    __syncthreads();
    if (threadIdx.x == 0) {
        int t = atomicAdd(&g_done2, 1);
        if (t == CGRID - 1) { g_done2 = 0; g_wl_cnt = 0; }
    }
}

extern "C" void kernel_launch(void* const* d_in, const int* in_sizes, int n_in,
                              void* d_out, int out_size) {
    const float* depth = (const float*)d_in[0];
    const float* obj   = (const float*)d_in[1];
    const float* gaze  = (const float*)d_in[2];
    const long long* hp = (const long long*)d_in[3];
    float* out = (float*)d_out;

    fused_kernel<<<NRED + NFILL, 256>>>(depth, obj, gaze, hp, out);
    cone_kernel<<<CGRID, 256>>>(depth, obj, out);
}